// round 1
// baseline (speedup 1.0000x reference)
#include <cuda_runtime.h>
#include <math.h>

#define N_TOT 8192
#define B_HALF 4096
#define D 128
// sqrt(log2(e) / T) with T = 0.5  => sqrt(2 * 1.4426950408889634)
#define VSCALE 1.6986436f
#define LN2F 0.6931471805599453f

// normalized + pre-scaled embeddings: v = (z/||z||) * sqrt(log2e/T)
__device__ float g_v[N_TOT * D];

__device__ __forceinline__ float ex2f(float x) {
    float y;
    asm("ex2.approx.f32 %0, %1;" : "=f"(y) : "f"(x));
    return y;
}

__global__ void zero_out_k(float* out) { out[0] = 0.0f; }

__global__ void normalize_k(const float* __restrict__ zi,
                            const float* __restrict__ zj) {
    int warp = (blockIdx.x * blockDim.x + threadIdx.x) >> 5;
    int lane = threadIdx.x & 31;
    if (warp >= N_TOT) return;
    const float* src = (warp < B_HALF) ? (zi + (size_t)warp * D)
                                       : (zj + (size_t)(warp - B_HALF) * D);
    float4 a = reinterpret_cast<const float4*>(src)[lane];
    float ss = a.x * a.x + a.y * a.y + a.z * a.z + a.w * a.w;
#pragma unroll
    for (int o = 16; o; o >>= 1) ss += __shfl_xor_sync(0xffffffffu, ss, o);
    float norm = fmaxf(sqrtf(ss), 1e-8f);
    float s = VSCALE / norm;
    float4 v = make_float4(a.x * s, a.y * s, a.z * s, a.w * s);
    reinterpret_cast<float4*>(g_v + (size_t)warp * D)[lane] = v;
}

// Each block: 64 rows x all 8192 columns. 256 threads, 4x4 microtile.
// smem: rows[64][128] (row-major), colsT[128][68] (k-major, padded).
#define CPAD 68

__global__ void simclr_main_k(float* __restrict__ out) {
    extern __shared__ float smem[];
    float* rows  = smem;             // 64*128
    float* colsT = smem + 64 * D;    // 128*CPAD

    int tid = threadIdx.x;
    int tx = tid & 15;       // column group (4 cols each)
    int ty = tid >> 4;       // row group (4 rows each, stride 16)
    int rb = blockIdx.x * 64;
    int prb = (rb + B_HALF) & (N_TOT - 1);   // column tile holding positive pairs

    // load this block's 64 row vectors
    for (int i = tid; i < 64 * D / 4; i += 256)
        reinterpret_cast<float4*>(rows)[i] =
            reinterpret_cast<const float4*>(g_v + (size_t)rb * D)[i];

    float rowsum[4] = {0.f, 0.f, 0.f, 0.f};
    float posv[4]   = {0.f, 0.f, 0.f, 0.f};

    for (int ct = 0; ct < N_TOT / 64; ct++) {
        int cb = ct * 64;
        __syncthreads();
        // load column tile, transposed to k-major with pad
        for (int it = tid; it < 64 * 32; it += 256) {
            int j  = it >> 5;
            int k4 = it & 31;
            float4 g = reinterpret_cast<const float4*>(g_v + (size_t)(cb + j) * D)[k4];
            int k = k4 * 4;
            colsT[(k + 0) * CPAD + j] = g.x;
            colsT[(k + 1) * CPAD + j] = g.y;
            colsT[(k + 2) * CPAD + j] = g.z;
            colsT[(k + 3) * CPAD + j] = g.w;
        }
        __syncthreads();

        float acc[4][4];
#pragma unroll
        for (int ri = 0; ri < 4; ri++)
#pragma unroll
            for (int ci = 0; ci < 4; ci++) acc[ri][ci] = 0.f;

#pragma unroll 8
        for (int k = 0; k < D; k++) {
            float4 c4 = *reinterpret_cast<float4*>(&colsT[k * CPAD + tx * 4]);
#pragma unroll
            for (int ri = 0; ri < 4; ri++) {
                float rv = rows[(ty + 16 * ri) * D + k];
                acc[ri][0] += rv * c4.x;
                acc[ri][1] += rv * c4.y;
                acc[ri][2] += rv * c4.z;
                acc[ri][3] += rv * c4.w;
            }
        }

        if (cb == rb || cb == prb) {
            // special tiles: self-mask and/or positive-pair capture
#pragma unroll
            for (int ri = 0; ri < 4; ri++) {
                int i  = rb + ty + 16 * ri;
                int pj = (i + B_HALF) & (N_TOT - 1);
#pragma unroll
                for (int ci = 0; ci < 4; ci++) {
                    int j = cb + tx * 4 + ci;
                    float d = acc[ri][ci];
                    float e = ex2f(d);
                    if (j == i) e = 0.f;
                    rowsum[ri] += e;
                    if (j == pj) posv[ri] = d * LN2F;  // back to natural-log units
                }
            }
        } else {
#pragma unroll
            for (int ri = 0; ri < 4; ri++) {
                float s = 0.f;
#pragma unroll
                for (int ci = 0; ci < 4; ci++) s += ex2f(acc[ri][ci]);
                rowsum[ri] += s;
            }
        }
    }

    __syncthreads();
    // cross-thread reduction of 16 partial sums per row (reuse smem)
    float* redS = smem;            // 64 * 17
    float* redP = smem + 64 * 17;  // 64 * 17
#pragma unroll
    for (int ri = 0; ri < 4; ri++) {
        int r = ty + 16 * ri;
        redS[r * 17 + tx] = rowsum[ri];
        redP[r * 17 + tx] = posv[ri];
    }
    __syncthreads();
    if (tid < 64) {
        float S = 0.f, p = 0.f;
#pragma unroll
        for (int t = 0; t < 16; t++) {
            S += redS[tid * 17 + t];
            p += redP[tid * 17 + t];
        }
        float loss = logf(S) - p;
        atomicAdd(out, loss * (1.0f / (float)N_TOT));
    }
}

extern "C" void kernel_launch(void* const* d_in, const int* in_sizes, int n_in,
                              void* d_out, int out_size) {
    const float* zi = (const float*)d_in[0];
    const float* zj = (const float*)d_in[1];
    float* out = (float*)d_out;

    size_t smem_bytes = (size_t)(64 * D + D * CPAD) * sizeof(float);  // 67584 B
    cudaFuncSetAttribute(simclr_main_k,
                         cudaFuncAttributeMaxDynamicSharedMemorySize,
                         (int)smem_bytes);

    zero_out_k<<<1, 1>>>(out);
    normalize_k<<<(N_TOT * 32 + 255) / 256, 256>>>(zi, zj);
    simclr_main_k<<<N_TOT / 64, 256, smem_bytes>>>(out);
}

// round 3
// speedup vs baseline: 10.5413x; 10.5413x over previous
#include <cuda_runtime.h>
#include <cuda_bf16.h>
#include <math.h>
#include <stdint.h>

#define N_TOT 8192
#define B_HALF 4096
#define D 128
// sqrt(log2(e)/T), T=0.5: fold temperature+log2e into normalization so the
// Gram accumulator is sim in log2-units: exp(sim)=ex2(acc), sim=acc*ln2.
#define VSCALE 1.6986436f
#define LN2F 0.69314718055994531f

// ---------------- device globals ----------------
__device__ __nv_bfloat16 g_vb[N_TOT * D];
__device__ float g_rowsum[N_TOT];
__device__ float g_pos[N_TOT];

// ---------------- helpers ----------------
__device__ __forceinline__ uint32_t smem_u32(const void* p) {
    uint32_t a;
    asm("{ .reg .u64 t; cvta.to.shared.u64 t, %1; cvt.u32.u64 %0, t; }" : "=r"(a) : "l"(p));
    return a;
}
__device__ __forceinline__ float ex2f(float x) {
    float y; asm("ex2.approx.f32 %0, %1;" : "=f"(y) : "f"(x)); return y;
}
__device__ __forceinline__ void ldsm_x4(uint32_t* r, uint32_t a) {
    asm volatile("ldmatrix.sync.aligned.m8n8.x4.shared.b16 {%0,%1,%2,%3}, [%4];"
                 : "=r"(r[0]), "=r"(r[1]), "=r"(r[2]), "=r"(r[3]) : "r"(a));
}
__device__ __forceinline__ void ldsm_x2t(uint32_t* r, uint32_t a) {
    asm volatile("ldmatrix.sync.aligned.m8n8.x2.trans.shared.b16 {%0,%1}, [%2];"
                 : "=r"(r[0]), "=r"(r[1]) : "r"(a));
}
__device__ __forceinline__ void mma16816(float* d, const uint32_t* a, const uint32_t* b) {
    asm volatile(
        "mma.sync.aligned.m16n8k16.row.col.f32.bf16.bf16.f32 "
        "{%0,%1,%2,%3}, {%4,%5,%6,%7}, {%8,%9}, {%0,%1,%2,%3};"
        : "+f"(d[0]), "+f"(d[1]), "+f"(d[2]), "+f"(d[3])
        : "r"(a[0]), "r"(a[1]), "r"(a[2]), "r"(a[3]), "r"(b[0]), "r"(b[1]));
}

// smem tile layout: row-major 128 rows x 256B, 16B chunks XOR-swizzled:
// addr(row, chunk) = row*256 + (chunk ^ (row & 7)) * 16
__device__ __forceinline__ uint32_t sw_addr(uint32_t base, int row, int chunk) {
    return base + row * 256 + ((chunk ^ (row & 7)) << 4);
}

// ---------------- kernels ----------------
__global__ void init_k(float* out) {
    int i = blockIdx.x * 1024 + threadIdx.x;
    if (i < N_TOT) g_rowsum[i] = 0.0f;
    if (i == 0) out[0] = 0.0f;
}

__global__ void normalize_k(const float* __restrict__ zi,
                            const float* __restrict__ zj) {
    int warp = (blockIdx.x * blockDim.x + threadIdx.x) >> 5;
    int lane = threadIdx.x & 31;
    if (warp >= N_TOT) return;
    const float* src = (warp < B_HALF) ? (zi + (size_t)warp * D)
                                       : (zj + (size_t)(warp - B_HALF) * D);
    float4 a = reinterpret_cast<const float4*>(src)[lane];
    float ss = a.x * a.x + a.y * a.y + a.z * a.z + a.w * a.w;
#pragma unroll
    for (int o = 16; o; o >>= 1) ss += __shfl_xor_sync(0xffffffffu, ss, o);
    float s = VSCALE / fmaxf(sqrtf(ss), 1e-8f);
    __nv_bfloat162 h0 = __floats2bfloat162_rn(a.x * s, a.y * s);
    __nv_bfloat162 h1 = __floats2bfloat162_rn(a.z * s, a.w * s);
    uint2 pk = make_uint2(*reinterpret_cast<uint32_t*>(&h0),
                          *reinterpret_cast<uint32_t*>(&h1));
    reinterpret_cast<uint2*>(g_vb + (size_t)warp * D)[lane] = pk;
}

// One CTA = 128x128 output tile at (rb=blockIdx.y, cb=blockIdx.x).
// 256 threads = 8 warps in a 2x4 grid; each warp computes 64 rows x 32 cols.
#define SMEM_BYTES 65536

__global__ void __launch_bounds__(256, 2) simclr_mma_k() {
    extern __shared__ char dynsm[];
    __shared__ float smrow[128];
    const uint32_t SA = smem_u32(dynsm);
    const uint32_t SB = SA + 32768;

    const int tid = threadIdx.x, wid = tid >> 5, lane = tid & 31;
    const int wr = wid >> 2, wc = wid & 3;     // warp row / col in 2x4 grid
    const int rb = blockIdx.y, cb = blockIdx.x;

    if (tid < 128) smrow[tid] = 0.0f;

    // load A rows [rb*128, +128) and B rows [cb*128, +128) into swizzled smem
    {
        const uint4* ga = reinterpret_cast<const uint4*>(g_vb + (size_t)rb * 128 * D);
        const uint4* gb = reinterpret_cast<const uint4*>(g_vb + (size_t)cb * 128 * D);
#pragma unroll
        for (int i = 0; i < 8; i++) {
            int idx = tid + i * 256;            // 0..2047
            int row = idx >> 4, ch = idx & 15;
            uint4 va = ga[idx];
            uint4 vb = gb[idx];
            uint32_t aa = sw_addr(SA, row, ch);
            uint32_t ab = sw_addr(SB, row, ch);
            asm volatile("st.shared.v4.b32 [%0], {%1,%2,%3,%4};"
                         :: "r"(aa), "r"(va.x), "r"(va.y), "r"(va.z), "r"(va.w) : "memory");
            asm volatile("st.shared.v4.b32 [%0], {%1,%2,%3,%4};"
                         :: "r"(ab), "r"(vb.x), "r"(vb.y), "r"(vb.z), "r"(vb.w) : "memory");
        }
    }
    __syncthreads();

    float acc[4][4][4];
#pragma unroll
    for (int mt = 0; mt < 4; mt++)
#pragma unroll
        for (int nt = 0; nt < 4; nt++)
#pragma unroll
            for (int r = 0; r < 4; r++) acc[mt][nt][r] = 0.0f;

    // ldmatrix lane addressing precomputation
    const int g = lane >> 3;                   // 0..3 quadrant for x4
    const int arow_off = (lane & 7) + ((g & 1) << 3);
    const int achunk_off = g >> 1;             // 0 or 1
    const int brow_off = lane & 7;
    const int bchunk_off = (lane >> 3) & 1;

#pragma unroll
    for (int k = 0; k < 8; k++) {              // k-step covers chunks 2k, 2k+1
        uint32_t afr[4][4];
#pragma unroll
        for (int mt = 0; mt < 4; mt++) {
            int row = wr * 64 + mt * 16 + arow_off;
            ldsm_x4(afr[mt], sw_addr(SA, row, 2 * k + achunk_off));
        }
        uint32_t bfr[4][2];
#pragma unroll
        for (int nt = 0; nt < 4; nt++) {
            int row = wc * 32 + nt * 8 + brow_off;
            ldsm_x2t(bfr[nt], sw_addr(SB, row, 2 * k + bchunk_off));
        }
#pragma unroll
        for (int mt = 0; mt < 4; mt++)
#pragma unroll
            for (int nt = 0; nt < 4; nt++)
                mma16816(acc[mt][nt], afr[mt], bfr[nt]);
    }

    // -------- epilogue: exp + masking + row-sum --------
    const bool self_tile = (rb == cb);
    const bool pos_tile = (cb == (rb ^ 32));
    const int lr4 = lane >> 2;                 // row within 8
    const int lc2 = (lane & 3) * 2;            // col pair base within 8

#pragma unroll
    for (int mt = 0; mt < 4; mt++) {
        float rs0 = 0.0f, rs1 = 0.0f;          // row sums for r and r+8
        int lrow0 = wr * 64 + mt * 16 + lr4;   // local row of c0,c1
#pragma unroll
        for (int nt = 0; nt < 4; nt++) {
            float v0 = acc[mt][nt][0], v1 = acc[mt][nt][1];
            float v2 = acc[mt][nt][2], v3 = acc[mt][nt][3];
            float e0 = ex2f(v0), e1 = ex2f(v1), e2 = ex2f(v2), e3 = ex2f(v3);
            if (self_tile | pos_tile) {
                int lcol0 = wc * 32 + nt * 8 + lc2;
                // c0: (lrow0, lcol0)  c1: (lrow0, lcol0+1)
                // c2: (lrow0+8, lcol0) c3: (lrow0+8, lcol0+1)
                if (self_tile) {
                    if (lcol0 == lrow0) e0 = 0.0f;
                    if (lcol0 + 1 == lrow0) e1 = 0.0f;
                    if (lcol0 == lrow0 + 8) e2 = 0.0f;
                    if (lcol0 + 1 == lrow0 + 8) e3 = 0.0f;
                } else {
                    int gr0 = rb * 128 + lrow0;
                    if (lcol0 == lrow0) g_pos[gr0] = v0 * LN2F;
                    if (lcol0 + 1 == lrow0) g_pos[gr0] = v1 * LN2F;
                    if (lcol0 == lrow0 + 8) g_pos[gr0 + 8] = v2 * LN2F;
                    if (lcol0 + 1 == lrow0 + 8) g_pos[gr0 + 8] = v3 * LN2F;
                }
            }
            rs0 += e0 + e1;
            rs1 += e2 + e3;
        }
        // reduce across the 4 lanes sharing a row (lane & 3)
        rs0 += __shfl_xor_sync(0xffffffffu, rs0, 1);
        rs0 += __shfl_xor_sync(0xffffffffu, rs0, 2);
        rs1 += __shfl_xor_sync(0xffffffffu, rs1, 1);
        rs1 += __shfl_xor_sync(0xffffffffu, rs1, 2);
        if ((lane & 3) == 0) {
            atomicAdd(&smrow[lrow0], rs0);
            atomicAdd(&smrow[lrow0 + 8], rs1);
        }
    }
    __syncthreads();
    if (tid < 128) atomicAdd(&g_rowsum[rb * 128 + tid], smrow[tid]);
}

__global__ void reduce_k(float* out) {
    __shared__ float sh[8];
    int i = blockIdx.x * 256 + threadIdx.x;    // grid 32 x 256 = 8192
    int wid = threadIdx.x >> 5, lid = threadIdx.x & 31;
    float l = logf(g_rowsum[i]) - g_pos[i];
#pragma unroll
    for (int o = 16; o; o >>= 1) l += __shfl_xor_sync(0xffffffffu, l, o);
    if (lid == 0) sh[wid] = l;
    __syncthreads();
    if (threadIdx.x == 0) {
        float s = 0.0f;
#pragma unroll
        for (int w = 0; w < 8; w++) s += sh[w];
        atomicAdd(out, s * (1.0f / (float)N_TOT));
    }
}

// ---------------- launch ----------------
extern "C" void kernel_launch(void* const* d_in, const int* in_sizes, int n_in,
                              void* d_out, int out_size) {
    const float* zi = (const float*)d_in[0];
    const float* zj = (const float*)d_in[1];
    float* out = (float*)d_out;

    cudaFuncSetAttribute(simclr_mma_k,
                         cudaFuncAttributeMaxDynamicSharedMemorySize, SMEM_BYTES);

    init_k<<<8, 1024>>>(out);
    normalize_k<<<(N_TOT * 32 + 255) / 256, 256>>>(zi, zj);
    dim3 grid(64, 64);
    simclr_mma_k<<<grid, 256, SMEM_BYTES>>>();
    reduce_k<<<32, 256>>>(out);
}

// round 4
// speedup vs baseline: 16.2715x; 1.5436x over previous
#include <cuda_runtime.h>
#include <cuda_fp16.h>
#include <math.h>
#include <stdint.h>

#define N_TOT 8192
#define B_HALF 4096
#define D 128
// sqrt(log2(e)/T), T=0.5: fold temperature+log2e into normalization so the
// Gram accumulator is sim in log2-units: exp(sim)=ex2(acc), sim=acc*ln2.
#define VSCALE 1.6986436f
#define LN2F 0.69314718055994531f

// ---------------- device globals ----------------
__device__ __half g_vh[N_TOT * D];
__device__ float g_rowsum[N_TOT];
__device__ float g_pos[N_TOT];

// ---------------- helpers ----------------
__device__ __forceinline__ uint32_t smem_u32(const void* p) {
    uint32_t a;
    asm("{ .reg .u64 t; cvta.to.shared.u64 t, %1; cvt.u32.u64 %0, t; }" : "=r"(a) : "l"(p));
    return a;
}
__device__ __forceinline__ float ex2f(float x) {
    float y; asm("ex2.approx.f32 %0, %1;" : "=f"(y) : "f"(x)); return y;
}
__device__ __forceinline__ void ldsm_x4(uint32_t* r, uint32_t a) {
    asm volatile("ldmatrix.sync.aligned.m8n8.x4.shared.b16 {%0,%1,%2,%3}, [%4];"
                 : "=r"(r[0]), "=r"(r[1]), "=r"(r[2]), "=r"(r[3]) : "r"(a));
}
__device__ __forceinline__ void ldsm_x2t(uint32_t* r, uint32_t a) {
    asm volatile("ldmatrix.sync.aligned.m8n8.x2.trans.shared.b16 {%0,%1}, [%2];"
                 : "=r"(r[0]), "=r"(r[1]) : "r"(a));
}
__device__ __forceinline__ void mma16816(float* d, const uint32_t* a, const uint32_t* b) {
    asm volatile(
        "mma.sync.aligned.m16n8k16.row.col.f32.f16.f16.f32 "
        "{%0,%1,%2,%3}, {%4,%5,%6,%7}, {%8,%9}, {%0,%1,%2,%3};"
        : "+f"(d[0]), "+f"(d[1]), "+f"(d[2]), "+f"(d[3])
        : "r"(a[0]), "r"(a[1]), "r"(a[2]), "r"(a[3]), "r"(b[0]), "r"(b[1]));
}

// smem tile: row-major 128 rows x 256B, 16B chunks XOR-swizzled.
__device__ __forceinline__ uint32_t sw_addr(uint32_t base, int row, int chunk) {
    return base + row * 256 + ((chunk ^ (row & 7)) << 4);
}

// ---------------- kernels ----------------
__global__ void normalize_k(const float* __restrict__ zi,
                            const float* __restrict__ zj, float* out) {
    int gt = blockIdx.x * blockDim.x + threadIdx.x;
    int warp = gt >> 5, lane = gt & 31;
    if (gt < N_TOT) g_rowsum[gt] = 0.0f;
    if (gt == 0) out[0] = 0.0f;
    if (warp >= N_TOT) return;
    const float* src = (warp < B_HALF) ? (zi + (size_t)warp * D)
                                       : (zj + (size_t)(warp - B_HALF) * D);
    float4 a = reinterpret_cast<const float4*>(src)[lane];
    float ss = a.x * a.x + a.y * a.y + a.z * a.z + a.w * a.w;
#pragma unroll
    for (int o = 16; o; o >>= 1) ss += __shfl_xor_sync(0xffffffffu, ss, o);
    float s = VSCALE / fmaxf(sqrtf(ss), 1e-8f);
    __half2 h0 = __floats2half2_rn(a.x * s, a.y * s);
    __half2 h1 = __floats2half2_rn(a.z * s, a.w * s);
    uint2 pk = make_uint2(*reinterpret_cast<uint32_t*>(&h0),
                          *reinterpret_cast<uint32_t*>(&h1));
    reinterpret_cast<uint2*>(g_vh + (size_t)warp * D)[lane] = pk;
}

// Triangle tiles only (rb <= cb). 256 threads = 8 warps (2x4), warp = 64x32.
// Off-diagonal tiles feed rowsums of block rb (row reduction) AND block cb
// (column reduction, by symmetry).
#define SMEM_BYTES 65536

__global__ void __launch_bounds__(256, 2) simclr_mma_k() {
    // wrapped-diagonal triangle map
    int x = blockIdx.x, y = blockIdx.y;
    if (y == 32 && x >= 32) return;
    int c = (x + y) & 63;
    const int rb = min(x, c), cb = max(x, c);

    extern __shared__ char dynsm[];
    __shared__ float smrow[128];
    __shared__ float smcol[128];
    const uint32_t SA = smem_u32(dynsm);
    const uint32_t SB = (rb == cb) ? SA : SA + 32768;

    const int tid = threadIdx.x, wid = tid >> 5, lane = tid & 31;
    const int wr = wid >> 2, wc = wid & 3;
    const bool self_tile = (rb == cb);
    const bool pos_tile = (cb == rb + 32);

    if (tid < 128) { smrow[tid] = 0.0f; smcol[tid] = 0.0f; }

    // load tiles into swizzled smem
    {
        const uint4* ga = reinterpret_cast<const uint4*>(g_vh + (size_t)rb * 128 * D);
        const uint4* gb = reinterpret_cast<const uint4*>(g_vh + (size_t)cb * 128 * D);
#pragma unroll
        for (int i = 0; i < 8; i++) {
            int idx = tid + i * 256;
            int row = idx >> 4, ch = idx & 15;
            uint4 va = ga[idx];
            uint32_t aa = sw_addr(SA, row, ch);
            asm volatile("st.shared.v4.b32 [%0], {%1,%2,%3,%4};"
                         :: "r"(aa), "r"(va.x), "r"(va.y), "r"(va.z), "r"(va.w) : "memory");
            if (!self_tile) {
                uint4 vb = gb[idx];
                uint32_t ab = sw_addr(SB, row, ch);
                asm volatile("st.shared.v4.b32 [%0], {%1,%2,%3,%4};"
                             :: "r"(ab), "r"(vb.x), "r"(vb.y), "r"(vb.z), "r"(vb.w) : "memory");
            }
        }
    }
    __syncthreads();

    float acc[4][4][4];
#pragma unroll
    for (int mt = 0; mt < 4; mt++)
#pragma unroll
        for (int nt = 0; nt < 4; nt++)
#pragma unroll
            for (int r = 0; r < 4; r++) acc[mt][nt][r] = 0.0f;

    const int g = lane >> 3;
    const int arow_off = (lane & 7) + ((g & 1) << 3);
    const int achunk_off = g >> 1;
    const int brow_off = lane & 7;
    const int bchunk_off = (lane >> 3) & 1;

#pragma unroll
    for (int k = 0; k < 8; k++) {
        uint32_t afr[4][4];
#pragma unroll
        for (int mt = 0; mt < 4; mt++) {
            int row = wr * 64 + mt * 16 + arow_off;
            ldsm_x4(afr[mt], sw_addr(SA, row, 2 * k + achunk_off));
        }
        uint32_t bfr[4][2];
#pragma unroll
        for (int nt = 0; nt < 4; nt++) {
            int row = wc * 32 + nt * 8 + brow_off;
            ldsm_x2t(bfr[nt], sw_addr(SB, row, 2 * k + bchunk_off));
        }
#pragma unroll
        for (int mt = 0; mt < 4; mt++)
#pragma unroll
            for (int nt = 0; nt < 4; nt++)
                mma16816(acc[mt][nt], afr[mt], bfr[nt]);
    }

    // -------- epilogue: exp + masking + row & column sums --------
    const int lr4 = lane >> 2;
    const int lc2 = (lane & 3) * 2;
    float csA[4] = {0.f, 0.f, 0.f, 0.f};    // column sums (col lc2 of each nt)
    float csB[4] = {0.f, 0.f, 0.f, 0.f};    // column sums (col lc2+1)

#pragma unroll
    for (int mt = 0; mt < 4; mt++) {
        float rs0 = 0.0f, rs1 = 0.0f;
        int lrow0 = wr * 64 + mt * 16 + lr4;
#pragma unroll
        for (int nt = 0; nt < 4; nt++) {
            float v0 = acc[mt][nt][0], v1 = acc[mt][nt][1];
            float v2 = acc[mt][nt][2], v3 = acc[mt][nt][3];
            float e0 = ex2f(v0), e1 = ex2f(v1), e2 = ex2f(v2), e3 = ex2f(v3);
            if (self_tile | pos_tile) {
                int lcol0 = wc * 32 + nt * 8 + lc2;
                if (self_tile) {
                    if (lcol0 == lrow0) e0 = 0.0f;
                    if (lcol0 + 1 == lrow0) e1 = 0.0f;
                    if (lcol0 == lrow0 + 8) e2 = 0.0f;
                    if (lcol0 + 1 == lrow0 + 8) e3 = 0.0f;
                } else {
                    // positive pairs on the local diagonal; symmetric, write both
                    int grR = rb * 128 + lrow0;
                    int grC = cb * 128 + lrow0;
                    if (lcol0 == lrow0)     { float p = v0 * LN2F; g_pos[grR] = p; g_pos[grC] = p; }
                    if (lcol0 + 1 == lrow0) { float p = v1 * LN2F; g_pos[grR] = p; g_pos[grC] = p; }
                    if (lcol0 == lrow0 + 8)     { float p = v2 * LN2F; g_pos[grR + 8] = p; g_pos[grC + 8] = p; }
                    if (lcol0 + 1 == lrow0 + 8) { float p = v3 * LN2F; g_pos[grR + 8] = p; g_pos[grC + 8] = p; }
                }
            }
            rs0 += e0 + e1;
            rs1 += e2 + e3;
            csA[nt] += e0 + e2;
            csB[nt] += e1 + e3;
        }
        rs0 += __shfl_xor_sync(0xffffffffu, rs0, 1);
        rs0 += __shfl_xor_sync(0xffffffffu, rs0, 2);
        rs1 += __shfl_xor_sync(0xffffffffu, rs1, 1);
        rs1 += __shfl_xor_sync(0xffffffffu, rs1, 2);
        if ((lane & 3) == 0) {
            atomicAdd(&smrow[lrow0], rs0);
            atomicAdd(&smrow[lrow0 + 8], rs1);
        }
    }

    if (!self_tile) {
        // reduce column sums across the 8 row-groups (lane bits 2..4)
#pragma unroll
        for (int nt = 0; nt < 4; nt++) {
            float a = csA[nt], b2 = csB[nt];
#pragma unroll
            for (int o = 4; o <= 16; o <<= 1) {
                a += __shfl_xor_sync(0xffffffffu, a, o);
                b2 += __shfl_xor_sync(0xffffffffu, b2, o);
            }
            if (lane < 4) {
                int col = wc * 32 + nt * 8 + lane * 2;
                atomicAdd(&smcol[col], a);
                atomicAdd(&smcol[col + 1], b2);
            }
        }
    }

    __syncthreads();
    if (tid < 128) {
        atomicAdd(&g_rowsum[rb * 128 + tid], smrow[tid]);
    } else if (!self_tile) {
        atomicAdd(&g_rowsum[cb * 128 + (tid - 128)], smcol[tid - 128]);
    }
}

__global__ void reduce_k(float* out) {
    __shared__ float sh[8];
    int i = blockIdx.x * 256 + threadIdx.x;    // grid 32 x 256 = 8192
    int wid = threadIdx.x >> 5, lid = threadIdx.x & 31;
    float l = logf(g_rowsum[i]) - g_pos[i];
#pragma unroll
    for (int o = 16; o; o >>= 1) l += __shfl_xor_sync(0xffffffffu, l, o);
    if (lid == 0) sh[wid] = l;
    __syncthreads();
    if (threadIdx.x == 0) {
        float s = 0.0f;
#pragma unroll
        for (int w = 0; w < 8; w++) s += sh[w];
        atomicAdd(out, s * (1.0f / (float)N_TOT));
    }
}

// ---------------- launch ----------------
extern "C" void kernel_launch(void* const* d_in, const int* in_sizes, int n_in,
                              void* d_out, int out_size) {
    const float* zi = (const float*)d_in[0];
    const float* zj = (const float*)d_in[1];
    float* out = (float*)d_out;

    cudaFuncSetAttribute(simclr_mma_k,
                         cudaFuncAttributeMaxDynamicSharedMemorySize, SMEM_BYTES);

    normalize_k<<<(N_TOT * 32 + 255) / 256, 256>>>(zi, zj, out);
    dim3 grid(64, 33);
    simclr_mma_k<<<grid, 256, SMEM_BYTES>>>();
    reduce_k<<<32, 256>>>(out);
}

// round 5
// speedup vs baseline: 16.4444x; 1.0106x over previous
#include <cuda_runtime.h>
#include <cuda_fp16.h>
#include <math.h>
#include <stdint.h>

#define N_TOT 8192
#define B_HALF 4096
#define D 128
#define NWORK 2080
// sqrt(log2(e)/T), T=0.5: fold temperature+log2e into normalization so the
// Gram accumulator is sim in log2-units: exp(sim)=ex2(acc), sim=acc*ln2.
#define VSCALE 1.6986436f
#define LN2F 0.69314718055994531f

// ---------------- device globals ----------------
__device__ __half g_vh[N_TOT * D];
__device__ float g_rowsum[N_TOT];
__device__ float g_pos[N_TOT];
__device__ unsigned int g_ctr;

// ---------------- helpers ----------------
__device__ __forceinline__ uint32_t smem_u32(const void* p) {
    uint32_t a;
    asm("{ .reg .u64 t; cvta.to.shared.u64 t, %1; cvt.u32.u64 %0, t; }" : "=r"(a) : "l"(p));
    return a;
}
__device__ __forceinline__ uint32_t ex2h2(uint32_t x) {
    uint32_t y; asm("ex2.approx.f16x2 %0, %1;" : "=r"(y) : "r"(x)); return y;
}
__device__ __forceinline__ uint32_t hadd2(uint32_t a, uint32_t b) {
    uint32_t d; asm("add.rn.f16x2 %0, %1, %2;" : "=r"(d) : "r"(a), "r"(b)); return d;
}
__device__ __forceinline__ float2 h22f2(uint32_t u) {
    __half2 h = *reinterpret_cast<__half2*>(&u);
    return __half22float2(h);
}
__device__ __forceinline__ void ldsm_x4(uint32_t* r, uint32_t a) {
    asm volatile("ldmatrix.sync.aligned.m8n8.x4.shared.b16 {%0,%1,%2,%3}, [%4];"
                 : "=r"(r[0]), "=r"(r[1]), "=r"(r[2]), "=r"(r[3]) : "r"(a));
}
__device__ __forceinline__ void ldsm_x4t(uint32_t* r, uint32_t a) {
    asm volatile("ldmatrix.sync.aligned.m8n8.x4.trans.shared.b16 {%0,%1,%2,%3}, [%4];"
                 : "=r"(r[0]), "=r"(r[1]), "=r"(r[2]), "=r"(r[3]) : "r"(a));
}
// fp16-accumulate HMMA
__device__ __forceinline__ void mma16816h(uint32_t* d, const uint32_t* a, const uint32_t* b) {
    asm volatile(
        "mma.sync.aligned.m16n8k16.row.col.f16.f16.f16.f16 "
        "{%0,%1}, {%2,%3,%4,%5}, {%6,%7}, {%0,%1};"
        : "+r"(d[0]), "+r"(d[1])
        : "r"(a[0]), "r"(a[1]), "r"(a[2]), "r"(a[3]), "r"(b[0]), "r"(b[1]));
}

// smem tile: row-major 128 rows x 256B, 16B chunks XOR-swizzled.
__device__ __forceinline__ uint32_t sw_addr(uint32_t base, int row, int chunk) {
    return base + row * 256 + ((chunk ^ (row & 7)) << 4);
}

// ---------------- kernels ----------------
__global__ void normalize_k(const float* __restrict__ zi,
                            const float* __restrict__ zj) {
    int gt = blockIdx.x * blockDim.x + threadIdx.x;
    int warp = gt >> 5, lane = gt & 31;
    if (gt < N_TOT) g_rowsum[gt] = 0.0f;
    if (gt == 0) g_ctr = 0u;
    if (warp >= N_TOT) return;
    const float* src = (warp < B_HALF) ? (zi + (size_t)warp * D)
                                       : (zj + (size_t)(warp - B_HALF) * D);
    float4 a = reinterpret_cast<const float4*>(src)[lane];
    float ss = a.x * a.x + a.y * a.y + a.z * a.z + a.w * a.w;
#pragma unroll
    for (int o = 16; o; o >>= 1) ss += __shfl_xor_sync(0xffffffffu, ss, o);
    float s = VSCALE / fmaxf(sqrtf(ss), 1e-8f);
    __half2 h0 = __floats2half2_rn(a.x * s, a.y * s);
    __half2 h1 = __floats2half2_rn(a.z * s, a.w * s);
    uint2 pk = make_uint2(*reinterpret_cast<uint32_t*>(&h0),
                          *reinterpret_cast<uint32_t*>(&h1));
    reinterpret_cast<uint2*>(g_vh + (size_t)warp * D)[lane] = pk;
}

#define SMEM_BYTES 65536

__global__ void __launch_bounds__(256, 3) simclr_mma_k(float* __restrict__ out) {
    // wrapped-diagonal triangle map: each unordered block pair exactly once
    int x = blockIdx.x, y = blockIdx.y;
    if (y == 32 && x >= 32) return;
    int c = (x + y) & 63;
    const int rb = min(x, c), cb = max(x, c);

    extern __shared__ char dynsm[];
    __shared__ float smrow[128];
    __shared__ float smcol[128];
    __shared__ unsigned int s_last;
    const uint32_t SA = smem_u32(dynsm);
    const bool self_tile = (rb == cb);
    const bool pos_tile = (cb == rb + 32);
    const uint32_t SB = self_tile ? SA : SA + 32768;

    const int tid = threadIdx.x, wid = tid >> 5, lane = tid & 31;
    const int wr = wid >> 2, wc = wid & 3;

    if (tid < 128) { smrow[tid] = 0.0f; smcol[tid] = 0.0f; }

    // load tiles into swizzled smem
    {
        const uint4* ga = reinterpret_cast<const uint4*>(g_vh + (size_t)rb * 128 * D);
        const uint4* gb = reinterpret_cast<const uint4*>(g_vh + (size_t)cb * 128 * D);
#pragma unroll
        for (int i = 0; i < 8; i++) {
            int idx = tid + i * 256;
            int row = idx >> 4, ch = idx & 15;
            uint4 va = ga[idx];
            uint32_t aa = sw_addr(SA, row, ch);
            asm volatile("st.shared.v4.b32 [%0], {%1,%2,%3,%4};"
                         :: "r"(aa), "r"(va.x), "r"(va.y), "r"(va.z), "r"(va.w) : "memory");
            if (!self_tile) {
                uint4 vb = gb[idx];
                uint32_t ab = sw_addr(SB, row, ch);
                asm volatile("st.shared.v4.b32 [%0], {%1,%2,%3,%4};"
                             :: "r"(ab), "r"(vb.x), "r"(vb.y), "r"(vb.z), "r"(vb.w) : "memory");
            }
        }
    }
    __syncthreads();

    uint32_t acc[4][4][2];
#pragma unroll
    for (int mt = 0; mt < 4; mt++)
#pragma unroll
        for (int nt = 0; nt < 4; nt++) { acc[mt][nt][0] = 0u; acc[mt][nt][1] = 0u; }

    const int g = lane >> 3;
    const int arow_off = (lane & 7) + ((g & 1) << 3);
    const int achunk_off = g >> 1;
    const int brow_off = (lane & 7) + ((lane >> 4) & 1) * 8;  // spans 2 nt blocks
    const int bchunk_off = (lane >> 3) & 1;

#pragma unroll
    for (int k = 0; k < 8; k++) {
        uint32_t afr[4][4];
#pragma unroll
        for (int mt = 0; mt < 4; mt++) {
            int row = wr * 64 + mt * 16 + arow_off;
            ldsm_x4(afr[mt], sw_addr(SA, row, 2 * k + achunk_off));
        }
        uint32_t bfr[4][2];
#pragma unroll
        for (int nb = 0; nb < 2; nb++) {   // x4.trans covers nt = 2nb, 2nb+1
            uint32_t r4[4];
            int row = wc * 32 + nb * 16 + brow_off;
            ldsm_x4t(r4, sw_addr(SB, row, 2 * k + bchunk_off));
            bfr[2 * nb][0] = r4[0]; bfr[2 * nb][1] = r4[1];
            bfr[2 * nb + 1][0] = r4[2]; bfr[2 * nb + 1][1] = r4[3];
        }
#pragma unroll
        for (int mt = 0; mt < 4; mt++)
#pragma unroll
            for (int nt = 0; nt < 4; nt++)
                mma16816h(acc[mt][nt], afr[mt], bfr[nt]);
    }

    // -------- epilogue --------
    const int lr4 = lane >> 2;
    const int lc2 = (lane & 3) * 2;

    if (self_tile | pos_tile) {
        // exact f32 path for the 96 special CTAs
        float csA[4] = {0.f, 0.f, 0.f, 0.f};
        float csB[4] = {0.f, 0.f, 0.f, 0.f};
#pragma unroll
        for (int mt = 0; mt < 4; mt++) {
            float rs0 = 0.0f, rs1 = 0.0f;
            int lrow0 = wr * 64 + mt * 16 + lr4;
#pragma unroll
            for (int nt = 0; nt < 4; nt++) {
                float2 v01 = h22f2(acc[mt][nt][0]);
                float2 v23 = h22f2(acc[mt][nt][1]);
                float e0 = exp2f(v01.x), e1 = exp2f(v01.y);
                float e2 = exp2f(v23.x), e3 = exp2f(v23.y);
                int lcol0 = wc * 32 + nt * 8 + lc2;
                if (self_tile) {
                    if (lcol0 == lrow0) e0 = 0.0f;
                    if (lcol0 + 1 == lrow0) e1 = 0.0f;
                    if (lcol0 == lrow0 + 8) e2 = 0.0f;
                    if (lcol0 + 1 == lrow0 + 8) e3 = 0.0f;
                } else {
                    int grR = rb * 128 + lrow0;
                    int grC = cb * 128 + lrow0;
                    if (lcol0 == lrow0)     { float p = v01.x * LN2F; g_pos[grR] = p; g_pos[grC] = p; }
                    if (lcol0 + 1 == lrow0) { float p = v01.y * LN2F; g_pos[grR] = p; g_pos[grC] = p; }
                    if (lcol0 == lrow0 + 8)     { float p = v23.x * LN2F; g_pos[grR + 8] = p; g_pos[grC + 8] = p; }
                    if (lcol0 + 1 == lrow0 + 8) { float p = v23.y * LN2F; g_pos[grR + 8] = p; g_pos[grC + 8] = p; }
                }
                rs0 += e0 + e1;
                rs1 += e2 + e3;
                csA[nt] += e0 + e2;
                csB[nt] += e1 + e3;
            }
            rs0 += __shfl_xor_sync(0xffffffffu, rs0, 1);
            rs0 += __shfl_xor_sync(0xffffffffu, rs0, 2);
            rs1 += __shfl_xor_sync(0xffffffffu, rs1, 1);
            rs1 += __shfl_xor_sync(0xffffffffu, rs1, 2);
            if ((lane & 3) == 0) {
                atomicAdd(&smrow[lrow0], rs0);
                atomicAdd(&smrow[lrow0 + 8], rs1);
            }
        }
        if (!self_tile) {
#pragma unroll
            for (int nt = 0; nt < 4; nt++) {
                float a = csA[nt], b2 = csB[nt];
#pragma unroll
                for (int o = 4; o <= 16; o <<= 1) {
                    a += __shfl_xor_sync(0xffffffffu, a, o);
                    b2 += __shfl_xor_sync(0xffffffffu, b2, o);
                }
                if (lane < 4) {
                    int col = wc * 32 + nt * 8 + lane * 2;
                    atomicAdd(&smcol[col], a);
                    atomicAdd(&smcol[col + 1], b2);
                }
            }
        }
    } else {
        // hot path: packed f16x2 exp + sums
        uint32_t cs[4] = {0u, 0u, 0u, 0u};
#pragma unroll
        for (int mt = 0; mt < 4; mt++) {
            uint32_t rp0 = 0u, rp1 = 0u;
#pragma unroll
            for (int nt = 0; nt < 4; nt++) {
                uint32_t e0 = ex2h2(acc[mt][nt][0]);
                uint32_t e1 = ex2h2(acc[mt][nt][1]);
                rp0 = hadd2(rp0, e0);
                rp1 = hadd2(rp1, e1);
                cs[nt] = hadd2(cs[nt], hadd2(e0, e1));
            }
            float2 f0 = h22f2(rp0);
            float2 f1 = h22f2(rp1);
            float rs0 = f0.x + f0.y, rs1 = f1.x + f1.y;
            rs0 += __shfl_xor_sync(0xffffffffu, rs0, 1);
            rs0 += __shfl_xor_sync(0xffffffffu, rs0, 2);
            rs1 += __shfl_xor_sync(0xffffffffu, rs1, 1);
            rs1 += __shfl_xor_sync(0xffffffffu, rs1, 2);
            int lrow0 = wr * 64 + mt * 16 + lr4;
            if ((lane & 3) == 0) {
                atomicAdd(&smrow[lrow0], rs0);
                atomicAdd(&smrow[lrow0 + 8], rs1);
            }
        }
#pragma unroll
        for (int nt = 0; nt < 4; nt++) {
            float2 cf = h22f2(cs[nt]);
            float a = cf.x, b2 = cf.y;
#pragma unroll
            for (int o = 4; o <= 16; o <<= 1) {
                a += __shfl_xor_sync(0xffffffffu, a, o);
                b2 += __shfl_xor_sync(0xffffffffu, b2, o);
            }
            if (lane < 4) {
                int col = wc * 32 + nt * 8 + lane * 2;
                atomicAdd(&smcol[col], a);
                atomicAdd(&smcol[col + 1], b2);
            }
        }
    }

    __syncthreads();
    if (tid < 128) {
        atomicAdd(&g_rowsum[rb * 128 + tid], smrow[tid]);
    } else if (!self_tile) {
        atomicAdd(&g_rowsum[cb * 128 + (tid - 128)], smcol[tid - 128]);
    }

    // -------- last-CTA fused reduction --------
    __threadfence();
    __syncthreads();
    if (tid == 0) s_last = (atomicAdd(&g_ctr, 1u) == NWORK - 1u);
    __syncthreads();
    if (s_last) {
        float part = 0.0f;
        for (int i = tid; i < N_TOT; i += 256)
            part += logf(g_rowsum[i]) - g_pos[i];
#pragma unroll
        for (int o = 16; o; o >>= 1) part += __shfl_xor_sync(0xffffffffu, part, o);
        if (lane == 0) smrow[wid] = part;
        __syncthreads();
        if (tid == 0) {
            float s = 0.0f;
#pragma unroll
            for (int w = 0; w < 8; w++) s += smrow[w];
            out[0] = s * (1.0f / (float)N_TOT);
        }
    }
}

// ---------------- launch ----------------
extern "C" void kernel_launch(void* const* d_in, const int* in_sizes, int n_in,
                              void* d_out, int out_size) {
    const float* zi = (const float*)d_in[0];
    const float* zj = (const float*)d_in[1];
    float* out = (float*)d_out;

    cudaFuncSetAttribute(simclr_mma_k,
                         cudaFuncAttributeMaxDynamicSharedMemorySize, SMEM_BYTES);

    normalize_k<<<(N_TOT * 32 + 255) / 256, 256>>>(zi, zj);
    dim3 grid(64, 33);
    simclr_mma_k<<<grid, 256, SMEM_BYTES>>>(out);
}